// round 1
// baseline (speedup 1.0000x reference)
#include <cuda_runtime.h>

// MLP_89498528514757 — fused recommender MLP, fp32.
// inputs (metadata order): user_ids[1024] i32, item_ids[1024] i32,
//   W1[150000*256] f32, b1[256], W2[256*128], b2[128],
//   W3[128*64], b3[64], W4[64*1], b4[1]
// output: out[1024] f32
//
// Grid: 128 blocks x 128 threads, 8 batch rows per block.
// All activations live in shared memory; weights stream from L2.

#define NUM_USERS 100000
#define BATCH     1024
#define ROWS      8          // batch rows per block

__global__ __launch_bounds__(128, 1)
void mlp_fused_kernel(const int*   __restrict__ user_ids,
                      const int*   __restrict__ item_ids,
                      const float* __restrict__ W1, const float* __restrict__ b1,
                      const float* __restrict__ W2, const float* __restrict__ b2,
                      const float* __restrict__ W3, const float* __restrict__ b3,
                      const float* __restrict__ W4, const float* __restrict__ b4,
                      float*       __restrict__ out)
{
    // h1 transposed: h1t[k][r], r contiguous (8 floats = 2 float4 per k)
    __shared__ float4 h1t[256][2];   // 8 KB
    __shared__ float4 h2t[128][2];   // 4 KB
    __shared__ float4 h3p[128][2];   // 4 KB  (layer-3 partials, 2 k-halves)
    __shared__ float  h3t[64 * 8];   // 2 KB  (h3[j][r])

    const int t    = threadIdx.x;     // 0..127
    const int row0 = blockIdx.x * ROWS;

    float* h1s = reinterpret_cast<float*>(h1t);

    // ---------------- Layer 1: embedding gather + b1 + ReLU ----------------
    // Each thread owns feature k = t and k = t+128 across all 8 rows.
    #pragma unroll
    for (int p = 0; p < 2; ++p) {
        const int k  = t + 128 * p;
        const float bk = b1[k];
        #pragma unroll
        for (int r = 0; r < ROWS; ++r) {
            const int u  = user_ids[row0 + r];
            const int it = item_ids[row0 + r];
            float v = W1[u * 256 + k] + W1[(NUM_USERS + it) * 256 + k] + bk;
            h1s[k * 8 + r] = fmaxf(v, 0.0f);
        }
    }
    __syncthreads();

    // ---------------- Layer 2: [8 x 256] @ W2[256 x 128] + b2, ReLU --------
    // Thread t computes output column j = t for all 8 rows.
    {
        const int j = t;
        float a0 = 0.f, a1 = 0.f, a2 = 0.f, a3 = 0.f;
        float a4 = 0.f, a5 = 0.f, a6 = 0.f, a7 = 0.f;
        #pragma unroll 8
        for (int k = 0; k < 256; ++k) {
            const float  w  = W2[k * 128 + j];      // coalesced across threads
            const float4 va = h1t[k][0];            // broadcast LDS.128
            const float4 vb = h1t[k][1];
            a0 = fmaf(va.x, w, a0);  a1 = fmaf(va.y, w, a1);
            a2 = fmaf(va.z, w, a2);  a3 = fmaf(va.w, w, a3);
            a4 = fmaf(vb.x, w, a4);  a5 = fmaf(vb.y, w, a5);
            a6 = fmaf(vb.z, w, a6);  a7 = fmaf(vb.w, w, a7);
        }
        const float bj = b2[j];
        h2t[j][0] = make_float4(fmaxf(a0 + bj, 0.f), fmaxf(a1 + bj, 0.f),
                                fmaxf(a2 + bj, 0.f), fmaxf(a3 + bj, 0.f));
        h2t[j][1] = make_float4(fmaxf(a4 + bj, 0.f), fmaxf(a5 + bj, 0.f),
                                fmaxf(a6 + bj, 0.f), fmaxf(a7 + bj, 0.f));
    }
    __syncthreads();

    // ---------------- Layer 3: [8 x 128] @ W3[128 x 64] + b3, ReLU ---------
    // Split k across two thread groups: j3 = t & 63, k-half = t >> 6.
    {
        const int j3 = t & 63;
        const int kh = t >> 6;
        float a0 = 0.f, a1 = 0.f, a2 = 0.f, a3 = 0.f;
        float a4 = 0.f, a5 = 0.f, a6 = 0.f, a7 = 0.f;
        #pragma unroll 8
        for (int kk = 0; kk < 64; ++kk) {
            const int    k  = kh * 64 + kk;
            const float  w  = W3[k * 64 + j3];
            const float4 va = h2t[k][0];
            const float4 vb = h2t[k][1];
            a0 = fmaf(va.x, w, a0);  a1 = fmaf(va.y, w, a1);
            a2 = fmaf(va.z, w, a2);  a3 = fmaf(va.w, w, a3);
            a4 = fmaf(vb.x, w, a4);  a5 = fmaf(vb.y, w, a5);
            a6 = fmaf(vb.z, w, a6);  a7 = fmaf(vb.w, w, a7);
        }
        h3p[t][0] = make_float4(a0, a1, a2, a3);
        h3p[t][1] = make_float4(a4, a5, a6, a7);
    }
    __syncthreads();

    // Combine the two k-halves, add b3, ReLU -> h3t[j][r]
    if (t < 64) {
        const float4 p0 = h3p[t][0], q0 = h3p[t + 64][0];
        const float4 p1 = h3p[t][1], q1 = h3p[t + 64][1];
        const float  bj = b3[t];
        h3t[t * 8 + 0] = fmaxf(p0.x + q0.x + bj, 0.f);
        h3t[t * 8 + 1] = fmaxf(p0.y + q0.y + bj, 0.f);
        h3t[t * 8 + 2] = fmaxf(p0.z + q0.z + bj, 0.f);
        h3t[t * 8 + 3] = fmaxf(p0.w + q0.w + bj, 0.f);
        h3t[t * 8 + 4] = fmaxf(p1.x + q1.x + bj, 0.f);
        h3t[t * 8 + 5] = fmaxf(p1.y + q1.y + bj, 0.f);
        h3t[t * 8 + 6] = fmaxf(p1.z + q1.z + bj, 0.f);
        h3t[t * 8 + 7] = fmaxf(p1.w + q1.w + bj, 0.f);
    }
    __syncthreads();

    // ---------------- Layer 4: [8 x 64] @ W4[64 x 1] + b4 ------------------
    if (t < ROWS) {
        float acc = b4[0];
        #pragma unroll 8
        for (int j = 0; j < 64; ++j)
            acc = fmaf(h3t[j * 8 + t], W4[j], acc);
        out[row0 + t] = acc;
    }
}

extern "C" void kernel_launch(void* const* d_in, const int* in_sizes, int n_in,
                              void* d_out, int out_size)
{
    const int*   user_ids = (const int*)  d_in[0];
    const int*   item_ids = (const int*)  d_in[1];
    const float* W1       = (const float*)d_in[2];
    const float* b1       = (const float*)d_in[3];
    const float* W2       = (const float*)d_in[4];
    const float* b2       = (const float*)d_in[5];
    const float* W3       = (const float*)d_in[6];
    const float* b3       = (const float*)d_in[7];
    const float* W4       = (const float*)d_in[8];
    const float* b4       = (const float*)d_in[9];
    float*       out      = (float*)d_out;

    mlp_fused_kernel<<<BATCH / ROWS, 128>>>(user_ids, item_ids,
                                            W1, b1, W2, b2, W3, b3, W4, b4, out);
}

// round 2
// speedup vs baseline: 1.3153x; 1.3153x over previous
#include <cuda_runtime.h>

// MLP_89498528514757 — fused recommender MLP, fp32. Round 2:
// parallelism bump: 256 blocks x 256 threads, 4 batch rows/block,
// split-K in layers 2 (2-way) and 3 (4-way), warp-shuffle layer 4.

#define NUM_USERS 100000
#define BATCH     1024
#define ROWS      4          // batch rows per block

__global__ __launch_bounds__(256)
void mlp_fused_kernel(const int*   __restrict__ user_ids,
                      const int*   __restrict__ item_ids,
                      const float* __restrict__ W1, const float* __restrict__ b1,
                      const float* __restrict__ W2, const float* __restrict__ b2,
                      const float* __restrict__ W3, const float* __restrict__ b3,
                      const float* __restrict__ W4, const float* __restrict__ b4,
                      float*       __restrict__ out)
{
    __shared__ float4 h1t[256];   // h1[k] for 4 rows        (4 KB)
    __shared__ float4 h2p[256];   // layer-2 k-split partials (4 KB)
    __shared__ float4 h2t[128];   // h2[k] for 4 rows         (2 KB)
    __shared__ float4 h3p[256];   // layer-3 k-split partials (4 KB)
    __shared__ float4 h3t[64];    // h3[j] for 4 rows         (1 KB)

    const int t    = threadIdx.x;       // 0..255
    const int row0 = blockIdx.x * ROWS;

    // ---------------- Layer 1: embedding gather + b1 + ReLU ----------------
    // Thread t owns feature k = t for all 4 rows (8 independent DRAM gathers).
    {
        const int k  = t;
        const int u0 = user_ids[row0 + 0], i0 = item_ids[row0 + 0];
        const int u1 = user_ids[row0 + 1], i1 = item_ids[row0 + 1];
        const int u2 = user_ids[row0 + 2], i2 = item_ids[row0 + 2];
        const int u3 = user_ids[row0 + 3], i3 = item_ids[row0 + 3];
        const float bk = b1[k];
        float4 h;
        h.x = fmaxf(W1[u0 * 256 + k] + W1[(NUM_USERS + i0) * 256 + k] + bk, 0.f);
        h.y = fmaxf(W1[u1 * 256 + k] + W1[(NUM_USERS + i1) * 256 + k] + bk, 0.f);
        h.z = fmaxf(W1[u2 * 256 + k] + W1[(NUM_USERS + i2) * 256 + k] + bk, 0.f);
        h.w = fmaxf(W1[u3 * 256 + k] + W1[(NUM_USERS + i3) * 256 + k] + bk, 0.f);
        h1t[k] = h;
    }
    __syncthreads();

    // ---------------- Layer 2: [4 x 256] @ W2[256 x 128], 2-way split-K ----
    {
        const int j  = t & 127;
        const int kh = t >> 7;                       // 0 or 1
        const float* __restrict__ w2p = W2 + (kh * 128) * 128 + j;
        float4 a = make_float4(0.f, 0.f, 0.f, 0.f);
        #pragma unroll 8
        for (int kk = 0; kk < 128; ++kk) {
            const float  w = w2p[kk * 128];          // coalesced LDG (L2)
            const float4 v = h1t[kh * 128 + kk];     // broadcast LDS.128
            a.x = fmaf(v.x, w, a.x);  a.y = fmaf(v.y, w, a.y);
            a.z = fmaf(v.z, w, a.z);  a.w = fmaf(v.w, w, a.w);
        }
        h2p[t] = a;
    }
    __syncthreads();
    if (t < 128) {
        const float4 p = h2p[t], q = h2p[t + 128];
        const float  b = b2[t];
        h2t[t] = make_float4(fmaxf(p.x + q.x + b, 0.f), fmaxf(p.y + q.y + b, 0.f),
                             fmaxf(p.z + q.z + b, 0.f), fmaxf(p.w + q.w + b, 0.f));
    }
    __syncthreads();

    // ---------------- Layer 3: [4 x 128] @ W3[128 x 64], 4-way split-K -----
    {
        const int j3 = t & 63;
        const int kq = t >> 6;                       // 0..3
        const float* __restrict__ w3p = W3 + (kq * 32) * 64 + j3;
        float4 a = make_float4(0.f, 0.f, 0.f, 0.f);
        #pragma unroll 8
        for (int kk = 0; kk < 32; ++kk) {
            const float  w = w3p[kk * 64];
            const float4 v = h2t[kq * 32 + kk];
            a.x = fmaf(v.x, w, a.x);  a.y = fmaf(v.y, w, a.y);
            a.z = fmaf(v.z, w, a.z);  a.w = fmaf(v.w, w, a.w);
        }
        h3p[t] = a;
    }
    __syncthreads();
    if (t < 64) {
        const float4 p0 = h3p[t],       p1 = h3p[t + 64];
        const float4 p2 = h3p[t + 128], p3 = h3p[t + 192];
        const float  b  = b3[t];
        h3t[t] = make_float4(fmaxf(p0.x + p1.x + p2.x + p3.x + b, 0.f),
                             fmaxf(p0.y + p1.y + p2.y + p3.y + b, 0.f),
                             fmaxf(p0.z + p1.z + p2.z + p3.z + b, 0.f),
                             fmaxf(p0.w + p1.w + p2.w + p3.w + b, 0.f));
    }
    __syncthreads();

    // ---------------- Layer 4: [4 x 64] @ W4[64 x 1] + b4 (warp 0) ---------
    if (t < 32) {
        const float  wa = W4[t], wb = W4[t + 32];
        const float4 va = h3t[t], vb = h3t[t + 32];
        float4 acc;
        acc.x = fmaf(va.x, wa, vb.x * wb);
        acc.y = fmaf(va.y, wa, vb.y * wb);
        acc.z = fmaf(va.z, wa, vb.z * wb);
        acc.w = fmaf(va.w, wa, vb.w * wb);
        #pragma unroll
        for (int off = 16; off > 0; off >>= 1) {
            acc.x += __shfl_down_sync(0xffffffffu, acc.x, off);
            acc.y += __shfl_down_sync(0xffffffffu, acc.y, off);
            acc.z += __shfl_down_sync(0xffffffffu, acc.z, off);
            acc.w += __shfl_down_sync(0xffffffffu, acc.w, off);
        }
        if (t == 0) {
            const float bb = b4[0];
            out[row0 + 0] = acc.x + bb;
            out[row0 + 1] = acc.y + bb;
            out[row0 + 2] = acc.z + bb;
            out[row0 + 3] = acc.w + bb;
        }
    }
}

extern "C" void kernel_launch(void* const* d_in, const int* in_sizes, int n_in,
                              void* d_out, int out_size)
{
    const int*   user_ids = (const int*)  d_in[0];
    const int*   item_ids = (const int*)  d_in[1];
    const float* W1       = (const float*)d_in[2];
    const float* b1       = (const float*)d_in[3];
    const float* W2       = (const float*)d_in[4];
    const float* b2       = (const float*)d_in[5];
    const float* W3       = (const float*)d_in[6];
    const float* b3       = (const float*)d_in[7];
    const float* W4       = (const float*)d_in[8];
    const float* b4       = (const float*)d_in[9];
    float*       out      = (float*)d_out;

    mlp_fused_kernel<<<BATCH / ROWS, 256>>>(user_ids, item_ids,
                                            W1, b1, W2, b2, W3, b3, W4, b4, out);
}

// round 3
// speedup vs baseline: 1.5940x; 1.2119x over previous
#include <cuda_runtime.h>

// MLP_89498528514757 — fused recommender MLP, fp32. Round 3:
// single wave: 128 blocks x 512 threads (16 warps/SM), ROWS=8.
// 4-way split-K layer 2, 8-way split-K layer 3.
// Cross-barrier prefetch: W2 chunk before layer-1 sync, W3 before layer-2
// sync, W4/biases at entry — post-barrier loops are LDS+FFMA only.

#define NUM_USERS 100000
#define BATCH     1024
#define ROWS      8

__global__ __launch_bounds__(512)
void mlp_fused_kernel(const int*   __restrict__ user_ids,
                      const int*   __restrict__ item_ids,
                      const float* __restrict__ W1, const float* __restrict__ b1,
                      const float* __restrict__ W2, const float* __restrict__ b2,
                      const float* __restrict__ W3, const float* __restrict__ b3,
                      const float* __restrict__ W4, const float* __restrict__ b4,
                      float*       __restrict__ out)
{
    __shared__ float4 h1t[256][2];   // h1[k], 8 rows            (8 KB)
    __shared__ float4 h2p[512][2];   // layer-2 partials          (16 KB)
    __shared__ float4 h2t[128][2];   // h2[k], 8 rows             (4 KB)
    __shared__ float4 h3p[512][2];   // layer-3 partials          (16 KB)
    __shared__ float4 h3t[64][2];    // h3[j], 8 rows             (2 KB)

    const int t    = threadIdx.x;        // 0..511
    const int row0 = blockIdx.x * ROWS;

    // ---- early scalar prefetches (overlap everything) ----
    const float bj2 = (t < 128) ? b2[t] : 0.f;
    const float bj3 = (t < 64)  ? b3[t] : 0.f;
    float w4a = 0.f, w4b = 0.f, bb4 = 0.f;
    if (t < 32) { w4a = W4[t]; w4b = W4[t + 32]; bb4 = b4[0]; }

    // ---- Layer-2 weight pointers + prefetch first 16 of 64 k-iters ----
    const int j2  = t & 127;
    const int kq2 = t >> 7;                         // 0..3  (k-quarter)
    const float* __restrict__ w2p = W2 + (kq2 * 64) * 128 + j2;
    float w2pre[16];
    #pragma unroll
    for (int i = 0; i < 16; ++i) w2pre[i] = w2p[i * 128];

    // ---------------- Layer 1: embedding gather + b1 + ReLU ----------------
    // Thread t: feature k = t&255, row-half rh = t>>8 (4 rows, 8 DRAM gathers)
    {
        const int k  = t & 255;
        const int rh = t >> 8;                      // 0 or 1
        const int rb = row0 + rh * 4;
        const int u0 = user_ids[rb + 0], i0 = item_ids[rb + 0];
        const int u1 = user_ids[rb + 1], i1 = item_ids[rb + 1];
        const int u2 = user_ids[rb + 2], i2 = item_ids[rb + 2];
        const int u3 = user_ids[rb + 3], i3 = item_ids[rb + 3];
        const float bk = b1[k];
        float4 h;
        h.x = fmaxf(W1[u0 * 256 + k] + W1[(NUM_USERS + i0) * 256 + k] + bk, 0.f);
        h.y = fmaxf(W1[u1 * 256 + k] + W1[(NUM_USERS + i1) * 256 + k] + bk, 0.f);
        h.z = fmaxf(W1[u2 * 256 + k] + W1[(NUM_USERS + i2) * 256 + k] + bk, 0.f);
        h.w = fmaxf(W1[u3 * 256 + k] + W1[(NUM_USERS + i3) * 256 + k] + bk, 0.f);
        h1t[k][rh] = h;
    }
    __syncthreads();

    // ---------------- Layer 2: [8 x 256] @ W2[256 x 128], 4-way split-K ----
    {
        float4 a0 = make_float4(0.f, 0.f, 0.f, 0.f);
        float4 a1 = make_float4(0.f, 0.f, 0.f, 0.f);
        // prefetched 16 iters (weights already in registers)
        #pragma unroll
        for (int kk = 0; kk < 16; ++kk) {
            const int   k = kq2 * 64 + kk;
            const float w = w2pre[kk];
            const float4 va = h1t[k][0], vb = h1t[k][1];
            a0.x = fmaf(va.x, w, a0.x);  a0.y = fmaf(va.y, w, a0.y);
            a0.z = fmaf(va.z, w, a0.z);  a0.w = fmaf(va.w, w, a0.w);
            a1.x = fmaf(vb.x, w, a1.x);  a1.y = fmaf(vb.y, w, a1.y);
            a1.z = fmaf(vb.z, w, a1.z);  a1.w = fmaf(vb.w, w, a1.w);
        }
        // remaining 48 iters, fully unrolled so ptxas batches the LDGs
        #pragma unroll
        for (int kk = 16; kk < 64; ++kk) {
            const int   k = kq2 * 64 + kk;
            const float w = w2p[kk * 128];
            const float4 va = h1t[k][0], vb = h1t[k][1];
            a0.x = fmaf(va.x, w, a0.x);  a0.y = fmaf(va.y, w, a0.y);
            a0.z = fmaf(va.z, w, a0.z);  a0.w = fmaf(va.w, w, a0.w);
            a1.x = fmaf(vb.x, w, a1.x);  a1.y = fmaf(vb.y, w, a1.y);
            a1.z = fmaf(vb.z, w, a1.z);  a1.w = fmaf(vb.w, w, a1.w);
        }
        h2p[t][0] = a0;
        h2p[t][1] = a1;
    }

    // ---- Layer-3 weight prefetch (all 16 iters) before the sync ----
    const int j3  = t & 63;
    const int k83 = t >> 6;                          // 0..7 (k-eighth)
    float w3pre[16];
    {
        const float* __restrict__ w3p = W3 + (k83 * 16) * 64 + j3;
        #pragma unroll
        for (int i = 0; i < 16; ++i) w3pre[i] = w3p[i * 64];
    }
    __syncthreads();

    // combine 4 layer-2 partials, +b2, ReLU
    if (t < 128) {
        const float4 p0 = h2p[t][0],       p1 = h2p[t + 128][0];
        const float4 p2 = h2p[t + 256][0], p3 = h2p[t + 384][0];
        const float4 q0 = h2p[t][1],       q1 = h2p[t + 128][1];
        const float4 q2 = h2p[t + 256][1], q3 = h2p[t + 384][1];
        h2t[t][0] = make_float4(
            fmaxf(p0.x + p1.x + p2.x + p3.x + bj2, 0.f),
            fmaxf(p0.y + p1.y + p2.y + p3.y + bj2, 0.f),
            fmaxf(p0.z + p1.z + p2.z + p3.z + bj2, 0.f),
            fmaxf(p0.w + p1.w + p2.w + p3.w + bj2, 0.f));
        h2t[t][1] = make_float4(
            fmaxf(q0.x + q1.x + q2.x + q3.x + bj2, 0.f),
            fmaxf(q0.y + q1.y + q2.y + q3.y + bj2, 0.f),
            fmaxf(q0.z + q1.z + q2.z + q3.z + bj2, 0.f),
            fmaxf(q0.w + q1.w + q2.w + q3.w + bj2, 0.f));
    }
    __syncthreads();

    // ---------------- Layer 3: [8 x 128] @ W3[128 x 64], 8-way split-K -----
    {
        float4 a0 = make_float4(0.f, 0.f, 0.f, 0.f);
        float4 a1 = make_float4(0.f, 0.f, 0.f, 0.f);
        #pragma unroll
        for (int kk = 0; kk < 16; ++kk) {
            const int   k = k83 * 16 + kk;
            const float w = w3pre[kk];
            const float4 va = h2t[k][0], vb = h2t[k][1];
            a0.x = fmaf(va.x, w, a0.x);  a0.y = fmaf(va.y, w, a0.y);
            a0.z = fmaf(va.z, w, a0.z);  a0.w = fmaf(va.w, w, a0.w);
            a1.x = fmaf(vb.x, w, a1.x);  a1.y = fmaf(vb.y, w, a1.y);
            a1.z = fmaf(vb.z, w, a1.z);  a1.w = fmaf(vb.w, w, a1.w);
        }
        h3p[t][0] = a0;
        h3p[t][1] = a1;
    }
    __syncthreads();

    // combine 8 layer-3 partials, +b3, ReLU
    if (t < 64) {
        float4 s0 = make_float4(bj3, bj3, bj3, bj3);
        float4 s1 = s0;
        #pragma unroll
        for (int s = 0; s < 8; ++s) {
            const float4 p = h3p[t + 64 * s][0];
            const float4 q = h3p[t + 64 * s][1];
            s0.x += p.x; s0.y += p.y; s0.z += p.z; s0.w += p.w;
            s1.x += q.x; s1.y += q.y; s1.z += q.z; s1.w += q.w;
        }
        h3t[t][0] = make_float4(fmaxf(s0.x, 0.f), fmaxf(s0.y, 0.f),
                                fmaxf(s0.z, 0.f), fmaxf(s0.w, 0.f));
        h3t[t][1] = make_float4(fmaxf(s1.x, 0.f), fmaxf(s1.y, 0.f),
                                fmaxf(s1.z, 0.f), fmaxf(s1.w, 0.f));
    }
    __syncthreads();

    // ---------------- Layer 4: [8 x 64] @ W4[64 x 1] + b4 (warp 0) ---------
    if (t < 32) {
        const float4 va0 = h3t[t][0],      va1 = h3t[t][1];
        const float4 vb0 = h3t[t + 32][0], vb1 = h3t[t + 32][1];
        float a0 = fmaf(va0.x, w4a, vb0.x * w4b);
        float a1 = fmaf(va0.y, w4a, vb0.y * w4b);
        float a2 = fmaf(va0.z, w4a, vb0.z * w4b);
        float a3 = fmaf(va0.w, w4a, vb0.w * w4b);
        float a4 = fmaf(va1.x, w4a, vb1.x * w4b);
        float a5 = fmaf(va1.y, w4a, vb1.y * w4b);
        float a6 = fmaf(va1.z, w4a, vb1.z * w4b);
        float a7 = fmaf(va1.w, w4a, vb1.w * w4b);
        #pragma unroll
        for (int off = 16; off > 0; off >>= 1) {
            a0 += __shfl_down_sync(0xffffffffu, a0, off);
            a1 += __shfl_down_sync(0xffffffffu, a1, off);
            a2 += __shfl_down_sync(0xffffffffu, a2, off);
            a3 += __shfl_down_sync(0xffffffffu, a3, off);
            a4 += __shfl_down_sync(0xffffffffu, a4, off);
            a5 += __shfl_down_sync(0xffffffffu, a5, off);
            a6 += __shfl_down_sync(0xffffffffu, a6, off);
            a7 += __shfl_down_sync(0xffffffffu, a7, off);
        }
        if (t == 0) {
            out[row0 + 0] = a0 + bb4;  out[row0 + 1] = a1 + bb4;
            out[row0 + 2] = a2 + bb4;  out[row0 + 3] = a3 + bb4;
            out[row0 + 4] = a4 + bb4;  out[row0 + 5] = a5 + bb4;
            out[row0 + 6] = a6 + bb4;  out[row0 + 7] = a7 + bb4;
        }
    }
}

extern "C" void kernel_launch(void* const* d_in, const int* in_sizes, int n_in,
                              void* d_out, int out_size)
{
    const int*   user_ids = (const int*)  d_in[0];
    const int*   item_ids = (const int*)  d_in[1];
    const float* W1       = (const float*)d_in[2];
    const float* b1       = (const float*)d_in[3];
    const float* W2       = (const float*)d_in[4];
    const float* b2       = (const float*)d_in[5];
    const float* W3       = (const float*)d_in[6];
    const float* b3       = (const float*)d_in[7];
    const float* W4       = (const float*)d_in[8];
    const float* b4       = (const float*)d_in[9];
    float*       out      = (float*)d_out;

    mlp_fused_kernel<<<BATCH / ROWS, 512>>>(user_ids, item_ids,
                                            W1, b1, W2, b2, W3, b3, W4, b4, out);
}